// round 10
// baseline (speedup 1.0000x reference)
#include <cuda_runtime.h>
#include <cuda_fp16.h>
#include <math.h>

#define T_STEPS 256
#define T_CHUNK 64
#define N_CHUNKS (T_STEPS / T_CHUNK)
#define BATCH   128
#define IN_SZ   512
#define HID     1024
#define OUT_SZ  512
#define G4      4096   // 4 gates * HID, interleaved col n = 4*j + g  (g: 0=f,1=i,2=c,3=o)
#define NROWS   (T_STEPS*BATCH)   // 32768
#define LSTM_BLOCKS 128

// ---------------- static device scratch ----------------
__device__ float  d_xproj[(size_t)T_CHUNK * BATCH * G4];   // 128 MB chunk-local, [tr*128+b][n]
__device__ __half d_x_hi[(size_t)NROWS * IN_SZ];           // x remapped [t*128+b][k]
__device__ __half d_x_lo[(size_t)NROWS * IN_SZ];
__device__ __half d_hs_hi[(size_t)NROWS * HID];            // [b*256+t][j]
__device__ __half d_hs_lo[(size_t)NROWS * HID];
__device__ float  d_c[BATCH * HID];                        // cell-state checkpoint
__device__ __half d_H_hi[2 * BATCH * HID];                 // ping-pong h, [buf][b][k]
__device__ __half d_H_lo[2 * BATCH * HID];
__device__ __half d_Wxi_hi[(size_t)G4 * IN_SZ];            // n-major [n][k]
__device__ __half d_Wxi_lo[(size_t)G4 * IN_SZ];
__device__ __half d_Wri_hi[(size_t)G4 * HID];
__device__ __half d_Wri_lo[(size_t)G4 * HID];
__device__ __half d_Wot_hi[(size_t)OUT_SZ * HID];
__device__ __half d_Wot_lo[(size_t)OUT_SZ * HID];
__device__ float  d_bi[G4];
__device__ unsigned long long d_bar;

// ---------------- helpers ----------------
__device__ __forceinline__ void mma_f16(float& d0, float& d1, float& d2, float& d3,
                                        unsigned a0, unsigned a1, unsigned a2, unsigned a3,
                                        unsigned b0, unsigned b1) {
    asm volatile(
        "mma.sync.aligned.m16n8k16.row.col.f32.f16.f16.f32 "
        "{%0,%1,%2,%3}, {%4,%5,%6,%7}, {%8,%9}, {%0,%1,%2,%3};\n"
        : "+f"(d0), "+f"(d1), "+f"(d2), "+f"(d3)
        : "r"(a0), "r"(a1), "r"(a2), "r"(a3), "r"(b0), "r"(b1));
}

__device__ __forceinline__ float sigf(float v) { return 1.0f / (1.0f + expf(-v)); }

__device__ __forceinline__ void split2(float v, __half& h, __half& l) {
    h = __float2half_rn(v);
    l = __float2half_rn(v - __half2float(h));
}

// ---------------- packing kernels (only harness pointers as args) ----------------
__global__ void pack_w(const float* __restrict__ Wf, const float* __restrict__ Wi,
                       const float* __restrict__ Wc, const float* __restrict__ Wo) {
    int idx = blockIdx.x * blockDim.x + threadIdx.x;      // over 4096*1536
    if (idx >= G4 * 1536) return;
    int k = idx % 1536, n = idx / 1536;
    int g = n & 3, j = n >> 2;
    const float* W = (g == 0) ? Wf : (g == 1) ? Wi : (g == 2) ? Wc : Wo;
    float v = W[j * 1536 + k];
    __half h, l; split2(v, h, l);
    if (k < IN_SZ) { d_Wxi_hi[(size_t)n * IN_SZ + k] = h; d_Wxi_lo[(size_t)n * IN_SZ + k] = l; }
    else { int kk = k - IN_SZ; d_Wri_hi[(size_t)n * HID + kk] = h; d_Wri_lo[(size_t)n * HID + kk] = l; }
}

__global__ void pack_x(const float* __restrict__ x) {
    int idx = blockIdx.x * blockDim.x + threadIdx.x;      // over 32768*512
    if (idx >= NROWS * IN_SZ) return;
    int k = idx & (IN_SZ - 1);
    int r = idx >> 9;                 // dest row r = t*128 + b
    int tt = r >> 7, b = r & 127;
    float v = x[((size_t)((b << 8) + tt)) * IN_SZ + k];
    __half h, l; split2(v, h, l);
    d_x_hi[idx] = h;
    d_x_lo[idx] = l;
}

__global__ void pack_misc(const float* __restrict__ bf, const float* __restrict__ bi_,
                          const float* __restrict__ bc, const float* __restrict__ bo,
                          const float* __restrict__ Wout) {
    int idx = blockIdx.x * blockDim.x + threadIdx.x;
    if (idx < OUT_SZ * HID) {                               // W_out is [o][k] n-major already
        __half h, l; split2(Wout[idx], h, l);
        d_Wot_hi[idx] = h; d_Wot_lo[idx] = l;
    }
    if (idx < 2 * BATCH * HID) {
        d_H_hi[idx] = __float2half_rn(0.f);
        d_H_lo[idx] = __float2half_rn(0.f);
    }
    if (idx < G4) {
        int g = idx & 3, j = idx >> 2;
        const float* b = (g == 0) ? bf : (g == 1) ? bi_ : (g == 2) ? bc : bo;
        d_bi[idx] = b[j];
    }
}

// ---------------- split-fp16 MMA GEMM body (pointers derived in DEVICE code) ----------------
// CTA tile 64x64, 8 warps = 4(m) x 2(n); warp tile m16 x n32; 16 accumulators/thread.
// C[r][n] = A[r][k] * B[n][k]^T + bias[n].
template<int KD>
__device__ __forceinline__ void gemm_body(const __half* __restrict__ Ahi,
                                          const __half* __restrict__ Alo,
                                          const __half* __restrict__ Bhi,
                                          const __half* __restrict__ Blo,
                                          const float* __restrict__ bias,
                                          float* __restrict__ C, int NDtot) {
    __shared__ __align__(16) __half Ash[2][64][40];
    __shared__ __align__(16) __half Asl[2][64][40];
    int tid = threadIdx.x, wid = tid >> 5, lane = tid & 31;
    int gg = lane >> 2, tg = lane & 3;
    int wm = (wid & 3) << 4;        // 4 m-warps * 16 rows
    int wn = (wid >> 2) << 5;       // 2 n-warps * 32 cols
    int m0 = blockIdx.y * 64;
    int n0 = blockIdx.x * 64;

    float acc[4][4];
#pragma unroll
    for (int b = 0; b < 4; b++)
#pragma unroll
        for (int q = 0; q < 4; q++) acc[b][q] = 0.f;

    int row = tid >> 2, seg = (tid & 3) << 3;      // 64 rows x 4 segs of 8 halves
    const __half* Arow_hi = Ahi + (size_t)(m0 + row) * KD + seg;
    const __half* Arow_lo = Alo + (size_t)(m0 + row) * KD + seg;
    uint4 ph = *(const uint4*)(Arow_hi);
    uint4 pl = *(const uint4*)(Arow_lo);
    const int NCH = KD / 32;

    for (int kc = 0; kc < NCH; kc++) {
        int buf = kc & 1;
        *(uint4*)&Ash[buf][row][seg] = ph;
        *(uint4*)&Asl[buf][row][seg] = pl;
        __syncthreads();
        if (kc + 1 < NCH) {
            ph = *(const uint4*)(Arow_hi + (kc + 1) * 32);
            pl = *(const uint4*)(Arow_lo + (kc + 1) * 32);
        }
        int k0 = kc * 32;
#pragma unroll
        for (int s = 0; s < 2; s++) {
            int ks = s * 16;
            unsigned ah0 = *(const unsigned*)&Ash[buf][wm + gg][ks + tg * 2];
            unsigned ah1 = *(const unsigned*)&Ash[buf][wm + gg + 8][ks + tg * 2];
            unsigned ah2 = *(const unsigned*)&Ash[buf][wm + gg][ks + tg * 2 + 8];
            unsigned ah3 = *(const unsigned*)&Ash[buf][wm + gg + 8][ks + tg * 2 + 8];
            unsigned al0 = *(const unsigned*)&Asl[buf][wm + gg][ks + tg * 2];
            unsigned al1 = *(const unsigned*)&Asl[buf][wm + gg + 8][ks + tg * 2];
            unsigned al2 = *(const unsigned*)&Asl[buf][wm + gg][ks + tg * 2 + 8];
            unsigned al3 = *(const unsigned*)&Asl[buf][wm + gg + 8][ks + tg * 2 + 8];
#pragma unroll
            for (int ni = 0; ni < 4; ni++) {
                int n = n0 + wn + ni * 8 + gg;
                const __half* bhp = Bhi + (size_t)n * KD + k0 + ks;
                const __half* blp = Blo + (size_t)n * KD + k0 + ks;
                unsigned b0 = *(const unsigned*)(bhp + tg * 2);
                unsigned b1 = *(const unsigned*)(bhp + tg * 2 + 8);
                unsigned l0 = *(const unsigned*)(blp + tg * 2);
                unsigned l1 = *(const unsigned*)(blp + tg * 2 + 8);
                mma_f16(acc[ni][0], acc[ni][1], acc[ni][2], acc[ni][3],
                        ah0, ah1, ah2, ah3, b0, b1);   // hi*hi
                mma_f16(acc[ni][0], acc[ni][1], acc[ni][2], acc[ni][3],
                        ah0, ah1, ah2, ah3, l0, l1);   // hi*lo
                mma_f16(acc[ni][0], acc[ni][1], acc[ni][2], acc[ni][3],
                        al0, al1, al2, al3, b0, b1);   // lo*hi
            }
        }
        __syncthreads();
    }

    int r1 = m0 + wm + gg;
#pragma unroll
    for (int ni = 0; ni < 4; ni++) {
        int col = n0 + wn + ni * 8 + tg * 2;
        float2 bz = *(const float2*)(bias + col);
        float2 o0 = make_float2(acc[ni][0] + bz.x, acc[ni][1] + bz.y);
        float2 o1 = make_float2(acc[ni][2] + bz.x, acc[ni][3] + bz.y);
        *(float2*)(C + (size_t)r1 * NDtot + col) = o0;
        *(float2*)(C + (size_t)(r1 + 8) * NDtot + col) = o1;
    }
}

// Concrete GEMM kernels: statics referenced by name IN DEVICE CODE (no host shadow bug).
__global__ void __launch_bounds__(256) gemm_xproj(int t0) {
    gemm_body<IN_SZ>(d_x_hi + (size_t)t0 * BATCH * IN_SZ,
                     d_x_lo + (size_t)t0 * BATCH * IN_SZ,
                     d_Wxi_hi, d_Wxi_lo, d_bi, d_xproj, G4);
}

__global__ void __launch_bounds__(256) gemm_out(const float* __restrict__ bias,
                                                float* __restrict__ C) {
    gemm_body<HID>(d_hs_hi, d_hs_lo, d_Wot_hi, d_Wot_lo, bias, C, OUT_SZ);
}

// ---------------- persistent MMA LSTM recurrence (one chunk of T_CHUNK steps) ----------------
__device__ __forceinline__ void grid_barrier() {
    __syncthreads();
    if (threadIdx.x == 0) {
        __threadfence();
        unsigned long long ticket = atomicAdd(&d_bar, 1ULL);
        unsigned long long target = (ticket / LSTM_BLOCKS + 1ULL) * (unsigned long long)LSTM_BLOCKS;
        while (true) {
            unsigned long long v;
            asm volatile("ld.global.acquire.gpu.u64 %0, [%1];" : "=l"(v) : "l"(&d_bar));
            if (v >= target) break;
            __nanosleep(32);
        }
    }
    __syncthreads();
}

__global__ void __launch_bounds__(256, 1) lstm_kernel(int t0) {
    __shared__ __align__(16) __half Ash[2][128][40];
    __shared__ __align__(16) __half Asl[2][128][40];
    int tid = threadIdx.x, wid = tid >> 5, lane = tid & 31;
    int gg = lane >> 2, tg = lane & 3;
    int moff = (wid >> 1) << 5;     // 4 m-warps * 32 batch rows
    int noff = (wid & 1) << 4;      // 2 n-warps * 16 cols
    int jb = blockIdx.x;            // cols jb*32 .. +31 (gate-interleaved)
    // loader: 256 threads cover 128 rows x 32 halves: 2 threads/row, 16 halves each (2x uint4)
    int row = tid >> 1, seg = (tid & 1) << 4;

    // cell state: lanes with even tg own values; 8 per thread
    float cst[8];
#pragma unroll
    for (int q = 0; q < 8; q++) cst[q] = 0.f;
    if (t0 != 0 && (tg & 1) == 0) {
#pragma unroll
        for (int mi = 0; mi < 2; mi++)
#pragma unroll
            for (int ni = 0; ni < 2; ni++) {
                int brow = moff + mi * 16 + gg;
                int nb = jb * 32 + noff + ni * 8 + tg * 2;
                int j = nb >> 2;
                int ci = ((mi << 1) | ni) << 1;
                cst[ci]     = d_c[brow * HID + j];
                cst[ci + 1] = d_c[(brow + 8) * HID + j];
            }
    }

    for (int t = t0; t < t0 + T_CHUNK; t++) {
        const __half* Hr_hi = d_H_hi + (((t + 1) & 1) << 17);
        const __half* Hr_lo = d_H_lo + (((t + 1) & 1) << 17);
        __half* Hw_hi = d_H_hi + ((t & 1) << 17);
        __half* Hw_lo = d_H_lo + ((t & 1) << 17);

        float acc[2][2][4];
#pragma unroll
        for (int a = 0; a < 2; a++)
#pragma unroll
            for (int b = 0; b < 2; b++)
#pragma unroll
                for (int q = 0; q < 4; q++) acc[a][b][q] = 0.f;

        const __half* hrow_hi = Hr_hi + row * HID + seg;
        const __half* hrow_lo = Hr_lo + row * HID + seg;
        uint4 ph0 = *(const uint4*)(hrow_hi);
        uint4 ph1 = *(const uint4*)(hrow_hi + 8);
        uint4 pl0 = *(const uint4*)(hrow_lo);
        uint4 pl1 = *(const uint4*)(hrow_lo + 8);

        for (int kc = 0; kc < 32; kc++) {
            int buf = kc & 1;
            *(uint4*)&Ash[buf][row][seg] = ph0;
            *(uint4*)&Ash[buf][row][seg + 8] = ph1;
            *(uint4*)&Asl[buf][row][seg] = pl0;
            *(uint4*)&Asl[buf][row][seg + 8] = pl1;
            __syncthreads();
            if (kc < 31) {
                ph0 = *(const uint4*)(hrow_hi + (kc + 1) * 32);
                ph1 = *(const uint4*)(hrow_hi + (kc + 1) * 32 + 8);
                pl0 = *(const uint4*)(hrow_lo + (kc + 1) * 32);
                pl1 = *(const uint4*)(hrow_lo + (kc + 1) * 32 + 8);
            }
            int k0 = kc * 32;
#pragma unroll
            for (int s = 0; s < 2; s++) {
                int ks = s * 16;
#pragma unroll
                for (int mi = 0; mi < 2; mi++) {
                    int rb = moff + mi * 16;
                    unsigned ah0 = *(const unsigned*)&Ash[buf][rb + gg][ks + tg * 2];
                    unsigned ah1 = *(const unsigned*)&Ash[buf][rb + gg + 8][ks + tg * 2];
                    unsigned ah2 = *(const unsigned*)&Ash[buf][rb + gg][ks + tg * 2 + 8];
                    unsigned ah3 = *(const unsigned*)&Ash[buf][rb + gg + 8][ks + tg * 2 + 8];
                    unsigned al0 = *(const unsigned*)&Asl[buf][rb + gg][ks + tg * 2];
                    unsigned al1 = *(const unsigned*)&Asl[buf][rb + gg + 8][ks + tg * 2];
                    unsigned al2 = *(const unsigned*)&Asl[buf][rb + gg][ks + tg * 2 + 8];
                    unsigned al3 = *(const unsigned*)&Asl[buf][rb + gg + 8][ks + tg * 2 + 8];
#pragma unroll
                    for (int ni = 0; ni < 2; ni++) {
                        int n = jb * 32 + noff + ni * 8 + gg;
                        const __half* bhp = d_Wri_hi + (size_t)n * HID + k0 + ks;
                        const __half* blp = d_Wri_lo + (size_t)n * HID + k0 + ks;
                        unsigned b0 = *(const unsigned*)(bhp + tg * 2);
                        unsigned b1 = *(const unsigned*)(bhp + tg * 2 + 8);
                        unsigned l0 = *(const unsigned*)(blp + tg * 2);
                        unsigned l1 = *(const unsigned*)(blp + tg * 2 + 8);
                        mma_f16(acc[mi][ni][0], acc[mi][ni][1], acc[mi][ni][2], acc[mi][ni][3],
                                ah0, ah1, ah2, ah3, b0, b1);
                        mma_f16(acc[mi][ni][0], acc[mi][ni][1], acc[mi][ni][2], acc[mi][ni][3],
                                ah0, ah1, ah2, ah3, l0, l1);
                        mma_f16(acc[mi][ni][0], acc[mi][ni][1], acc[mi][ni][2], acc[mi][ni][3],
                                al0, al1, al2, al3, b0, b1);
                    }
                }
            }
            __syncthreads();
        }

        // epilogue: add x-projection, gates, update c, emit h (split halves)
        int tr = t - t0;
#pragma unroll
        for (int mi = 0; mi < 2; mi++) {
#pragma unroll
            for (int ni = 0; ni < 2; ni++) {
                int brow = moff + mi * 16 + gg;
                int nb = jb * 32 + noff + ni * 8 + tg * 2;
                float2 xp0 = *(const float2*)(d_xproj + (size_t)(tr * 128 + brow) * G4 + nb);
                float2 xp1 = *(const float2*)(d_xproj + (size_t)(tr * 128 + brow + 8) * G4 + nb);
                float p0 = acc[mi][ni][0] + xp0.x;
                float p1 = acc[mi][ni][1] + xp0.y;
                float p2 = acc[mi][ni][2] + xp1.x;
                float p3 = acc[mi][ni][3] + xp1.y;
                // partner lane (tg^1) holds (c~, o) pre-activations for the same j
                float q0 = __shfl_xor_sync(0xffffffffu, p0, 1);
                float q1 = __shfl_xor_sync(0xffffffffu, p1, 1);
                float q2 = __shfl_xor_sync(0xffffffffu, p2, 1);
                float q3 = __shfl_xor_sync(0xffffffffu, p3, 1);
                if ((tg & 1) == 0) {
                    int j = nb >> 2;
                    int ci = ((mi << 1) | ni) << 1;
                    {
                        float fg = sigf(p0), ii = sigf(p1), cc = tanhf(q0), oo = sigf(q1);
                        float cn = fg * cst[ci] + ii * cc;
                        cst[ci] = cn;
                        float h = oo * tanhf(cn);
                        __half hh, hl; split2(h, hh, hl);
                        Hw_hi[brow * HID + j] = hh;
                        Hw_lo[brow * HID + j] = hl;
                        size_t hsi = ((size_t)brow * T_STEPS + t) * HID + j;
                        d_hs_hi[hsi] = hh;
                        d_hs_lo[hsi] = hl;
                    }
                    {
                        float fg = sigf(p2), ii = sigf(p3), cc = tanhf(q2), oo = sigf(q3);
                        float cn = fg * cst[ci + 1] + ii * cc;
                        cst[ci + 1] = cn;
                        float h = oo * tanhf(cn);
                        __half hh, hl; split2(h, hh, hl);
                        Hw_hi[(brow + 8) * HID + j] = hh;
                        Hw_lo[(brow + 8) * HID + j] = hl;
                        size_t hsi = ((size_t)(brow + 8) * T_STEPS + t) * HID + j;
                        d_hs_hi[hsi] = hh;
                        d_hs_lo[hsi] = hl;
                    }
                }
            }
        }
        grid_barrier();
    }

    // checkpoint cell state for the next chunk
    if ((tg & 1) == 0) {
#pragma unroll
        for (int mi = 0; mi < 2; mi++)
#pragma unroll
            for (int ni = 0; ni < 2; ni++) {
                int brow = moff + mi * 16 + gg;
                int nb = jb * 32 + noff + ni * 8 + tg * 2;
                int j = nb >> 2;
                int ci = ((mi << 1) | ni) << 1;
                d_c[brow * HID + j] = cst[ci];
                d_c[(brow + 8) * HID + j] = cst[ci + 1];
            }
    }
}

// ---------------- launch (NO device symbols passed from host) ----------------
extern "C" void kernel_launch(void* const* d_in, const int* in_sizes, int n_in,
                              void* d_out, int out_size) {
    const float* x    = (const float*)d_in[0];
    const float* W_f  = (const float*)d_in[1];
    const float* b_f  = (const float*)d_in[2];
    const float* W_i  = (const float*)d_in[3];
    const float* b_i  = (const float*)d_in[4];
    const float* W_c  = (const float*)d_in[5];
    const float* b_c  = (const float*)d_in[6];
    const float* W_o  = (const float*)d_in[7];
    const float* b_o  = (const float*)d_in[8];
    const float* W_out= (const float*)d_in[9];
    const float* bout = (const float*)d_in[10];
    float* out = (float*)d_out;

    pack_w   <<<(G4 * 1536 + 255) / 256, 256>>>(W_f, W_i, W_c, W_o);
    pack_x   <<<(NROWS * IN_SZ + 255) / 256, 256>>>(x);
    pack_misc<<<(OUT_SZ * HID + 255) / 256, 256>>>(b_f, b_i, b_c, b_o, W_out);

    for (int ch = 0; ch < N_CHUNKS; ch++) {
        int t0 = ch * T_CHUNK;
        // input projection for this chunk: [8192 x 512] @ [512 x 4096] + bias (MMA)
        gemm_xproj<<<dim3(G4 / 64, (T_CHUNK * BATCH) / 64), 256>>>(t0);
        // recurrence for this chunk (MMA)
        lstm_kernel<<<LSTM_BLOCKS, 256>>>(t0);
    }

    // output projection: [32768 x 1024] @ [1024 x 512] + b_out (MMA)
    gemm_out<<<dim3(OUT_SZ / 64, NROWS / 64), 256>>>(bout, out);
}